// round 11
// baseline (speedup 1.0000x reference)
#include <cuda_runtime.h>
#include <cuda_fp16.h>
#include <math.h>
#include <stdint.h>

#define BATCH   128
#define EMBED   512
#define HIDDEN  512
#define VOCAB   32000
#define TSTEPS  20
#define VTILE   64
#define NVBLK2  (VOCAB/VTILE)   // 500 logits blocks

// ---------------------------------------------------------------------------
__device__ float  g_hnew[BATCH * HIDDEN];
__device__ float  g_c[BATCH * HIDDEN];
__device__ float  g_p1v[NVBLK2 * BATCH];
__device__ int    g_p1i[NVBLK2 * BATCH];
__device__ float  g_p2v[NVBLK2 * BATCH];
__device__ __half g_W1[VOCAB * 512];        // fp16(W_fc)
__device__ __half g_hn1[BATCH * 512];       // fp16(h) for logits
__device__ __half g_W1c[2048 * 1024];       // hi split of Wcat=[Wih|Whh]
__device__ __half g_Wsc[2048 * 1024];       // fp16(W1 + W2)  (W2 = residual*1024)
__device__ __half g_xh1[BATCH * 1024];      // hi split of [x|h]
__device__ __half g_xhs[BATCH * 1024];      // fp16(x1 + x2)
__device__ float  g_bias[2048];

__device__ __forceinline__ float sigf(float x) { return 1.0f / (1.0f + expf(-x)); }

// ---------------------------------------------------------------------------
__device__ __forceinline__ uint32_t smem_u32(const void* p) {
    uint32_t a;
    asm("{ .reg .u64 t; cvta.to.shared.u64 t, %1; cvt.u32.u64 %0, t; }" : "=r"(a) : "l"(p));
    return a;
}
__device__ __forceinline__ void cp16(uint32_t dst, const void* src) {
    asm volatile("cp.async.cg.shared.global [%0], [%1], 16;" :: "r"(dst), "l"(src) : "memory");
}
#define CP_COMMIT() asm volatile("cp.async.commit_group;" ::: "memory")
template <int N> __device__ __forceinline__ void cp_wait() {
    asm volatile("cp.async.wait_group %0;" :: "n"(N) : "memory");
}
__device__ __forceinline__ void ldsm4(uint32_t* r, uint32_t a) {
    asm volatile("ldmatrix.sync.aligned.m8n8.x4.shared.b16 {%0,%1,%2,%3}, [%4];"
                 : "=r"(r[0]), "=r"(r[1]), "=r"(r[2]), "=r"(r[3]) : "r"(a));
}
__device__ __forceinline__ void mma16816(float* d, const uint32_t* a, const uint32_t* b) {
    asm volatile(
        "mma.sync.aligned.m16n8k16.row.col.f32.f16.f16.f32 "
        "{%0,%1,%2,%3}, {%4,%5,%6,%7}, {%8,%9}, {%0,%1,%2,%3};"
        : "+f"(d[0]), "+f"(d[1]), "+f"(d[2]), "+f"(d[3])
        : "r"(a[0]), "r"(a[1]), "r"(a[2]), "r"(a[3]), "r"(b[0]), "r"(b[1]));
}

// ---------------------------------------------------------------------------
__global__ void init_kernel(const float* __restrict__ features) {
    int b = blockIdx.x, t = threadIdx.x;
    for (int k = t; k < 512; k += 256) {
        float x = features[b * 512 + k];
        __half x1 = __float2half_rn(x);
        __half x2 = __float2half_rn((x - __half2float(x1)) * 1024.0f);
        g_xh1[b * 1024 + k] = x1;
        g_xhs[b * 1024 + k] = __float2half_rn(__half2float(x1) + __half2float(x2));
        g_xh1[b * 1024 + 512 + k] = __float2half_rn(0.0f);
        g_xhs[b * 1024 + 512 + k] = __float2half_rn(0.0f);
        g_c[b * 512 + k]    = 0.0f;
        g_hnew[b * 512 + k] = 0.0f;
        g_hn1[b * 512 + k]  = __float2half_rn(0.0f);
    }
}

__global__ void wsplit_kernel(const float* __restrict__ Wfc) {
    size_t i = (size_t)blockIdx.x * blockDim.x + threadIdx.x;
    float4 v = ((const float4*)Wfc)[i];
    __half2* w1 = (__half2*)g_W1;
    w1[i * 2]     = __halves2half2(__float2half_rn(v.x), __float2half_rn(v.y));
    w1[i * 2 + 1] = __halves2half2(__float2half_rn(v.z), __float2half_rn(v.w));
}

__global__ void wsplit2_kernel(const float* __restrict__ Wih,
                               const float* __restrict__ Whh,
                               const float* __restrict__ bih,
                               const float* __restrict__ bhh) {
    size_t i = (size_t)blockIdx.x * blockDim.x + threadIdx.x;
    int m  = (int)(i >> 8);
    int kq = ((int)i & 255) * 4;
    float4 v = (kq < 512) ? *(const float4*)(Wih + (size_t)m * 512 + kq)
                          : *(const float4*)(Whh + (size_t)m * 512 + kq - 512);
    float vv[4] = {v.x, v.y, v.z, v.w};
    __half h1[4], hs[4];
#pragma unroll
    for (int q = 0; q < 4; ++q) {
        h1[q] = __float2half_rn(vv[q]);
        float r = (vv[q] - __half2float(h1[q])) * 1024.0f;
        __half h2 = __float2half_rn(r);
        hs[q] = __float2half_rn(__half2float(h1[q]) + __half2float(h2));
    }
    __half2* w1 = (__half2*)(g_W1c + (size_t)m * 1024 + kq);
    __half2* ws = (__half2*)(g_Wsc + (size_t)m * 1024 + kq);
    w1[0] = __halves2half2(h1[0], h1[1]);
    w1[1] = __halves2half2(h1[2], h1[3]);
    ws[0] = __halves2half2(hs[0], hs[1]);
    ws[1] = __halves2half2(hs[2], hs[3]);
    if (kq == 0) g_bias[m] = bih[m] + bhh[m];
}

// ---------------------------------------------------------------------------
// HMMA gates, TWO passes: d0 = W1*x1, ds = Ws*xs;
// gate = d0*(1-2^-10) + ds*2^-10 + bias. Tile 32 gate-rows x 32 batch.
#define GKC     64
#define GROWB   144
#define GW_T    (32 * GROWB)                 // 4608
#define GB_T    (32 * GROWB)
#define GSTAGE  (2 * GW_T + 2 * GB_T)        // 18432
#define SMEM_G  (3 * GSTAGE)                 // 55296

__global__ __launch_bounds__(128, 3) void gates_mma_kernel() {
    extern __shared__ char smem[];
    const uint32_t sb = smem_u32(smem);
    const int tid = threadIdx.x;
    const int wid = tid >> 5;
    const int lane = tid & 31;
    const int j0 = blockIdx.x * 8;
    const int n0 = blockIdx.y * 32;
    const int vrow0 = (wid & 1) * 16;
    const int bcol0 = (wid >> 1) * 16;

    float d0[2][4] = {};
    float ds[2][4] = {};

    auto load_stage = [&](int buf, int k0) {
        const uint32_t st = sb + buf * GSTAGE;
#pragma unroll
        for (int i = 0; i < 8; ++i) {
            int lin = i * 128 + tid;
            if (lin < 512) {
                int snd = lin >= 256;
                int idx = lin & 255;
                int r = idx >> 3, c = idx & 7;
                int m = (r >> 3) * 512 + j0 + (r & 7);
                const __half* src = (snd ? g_Wsc : g_W1c) + (size_t)m * 1024 + k0 + c * 8;
                cp16(st + snd * GW_T + r * GROWB + c * 16, src);
            } else {
                int rel = lin - 512;
                int snd = rel >= 256;
                int idx = rel & 255;
                int r = idx >> 3, c = idx & 7;
                const __half* src = (snd ? g_xhs : g_xh1) + (size_t)(n0 + r) * 1024 + k0 + c * 8;
                cp16(st + 2 * GW_T + snd * GB_T + r * GROWB + c * 16, src);
            }
        }
        CP_COMMIT();
    };

    load_stage(0, 0);
    load_stage(1, GKC);

    for (int kc = 0; kc < 16; ++kc) {
        if (kc < 15) cp_wait<1>(); else cp_wait<0>();
        __syncthreads();
        if (kc + 2 < 16) load_stage((kc + 2) % 3, (kc + 2) * GKC);
        const uint32_t st = sb + (kc % 3) * GSTAGE;
#pragma unroll
        for (int ks = 0; ks < 4; ++ks) {
            const uint32_t kb = ks * 32;
            const int mat = lane >> 3;
            uint32_t a1[4], as[4];
            {
                const uint32_t row = vrow0 + (mat & 1) * 8 + (lane & 7);
                const uint32_t ao = row * GROWB + kb + (mat >> 1) * 16;
                ldsm4(a1, st + ao);
                ldsm4(as, st + GW_T + ao);
            }
            uint32_t b1[2][2], bs[2][2];
            {
                const uint32_t row = bcol0 + (mat >> 1) * 8 + (lane & 7);
                const uint32_t bo = row * GROWB + kb + (mat & 1) * 16;
                uint32_t r[4];
                ldsm4(r, st + 2 * GW_T + bo);
                b1[0][0] = r[0]; b1[0][1] = r[1]; b1[1][0] = r[2]; b1[1][1] = r[3];
                ldsm4(r, st + 2 * GW_T + GB_T + bo);
                bs[0][0] = r[0]; bs[0][1] = r[1]; bs[1][0] = r[2]; bs[1][1] = r[3];
            }
#pragma unroll
            for (int nf = 0; nf < 2; ++nf) {
                mma16816(d0[nf], a1, b1[nf]);
                mma16816(ds[nf], as, bs[nf]);
            }
        }
    }

    __syncthreads();
    float* sg = (float*)smem;   // [32][33]
    const int r0 = vrow0 + (lane >> 2);
    const int r1 = r0 + 8;
    const float c0 = 0.9990234375f, c1 = 0.0009765625f;
#pragma unroll
    for (int nf = 0; nf < 2; ++nf) {
        const int c = bcol0 + nf * 8 + 2 * (lane & 3);
        sg[r0 * 33 + c]     = d0[nf][0] * c0 + ds[nf][0] * c1;
        sg[r0 * 33 + c + 1] = d0[nf][1] * c0 + ds[nf][1] * c1;
        sg[r1 * 33 + c]     = d0[nf][2] * c0 + ds[nf][2] * c1;
        sg[r1 * 33 + c + 1] = d0[nf][3] * c0 + ds[nf][3] * c1;
    }
    __syncthreads();
#pragma unroll
    for (int q = 0; q < 2; ++q) {
        const int idx = tid * 2 + q;
        const int jl = idx >> 5;
        const int bl = idx & 31;
        const int j = j0 + jl;
        const int b = n0 + bl;
        float ig = sigf(sg[(jl)      * 33 + bl] + g_bias[j]);
        float fg = sigf(sg[(8 + jl)  * 33 + bl] + g_bias[512 + j]);
        float gg = tanhf(sg[(16 + jl) * 33 + bl] + g_bias[1024 + j]);
        float og = sigf(sg[(24 + jl) * 33 + bl] + g_bias[1536 + j]);
        float c = fg * g_c[b * 512 + j] + ig * gg;
        g_c[b * 512 + j] = c;
        float h = og * tanhf(c);
        g_hnew[b * 512 + j] = h;
        g_hn1[b * 512 + j] = __float2half_rn(h);
    }
}

// ---------------------------------------------------------------------------
// HMMA approx logits: per CTA 64v x 128b, 128 threads (warp tile 32x64).
// K-chunk 32, 3-stage ring (46KB) -> 4 CTAs/SM. Epilogue per-column top-2.
#define KC      32
#define ROWB    80                  // 32 halves (64B) + 16B pad
#define WTILEB  (VTILE * ROWB)      // 5120
#define HTILEB  (128 * ROWB)        // 10240
#define STAGEB  (WTILEB + HTILEB)   // 15360
#define SMEM_LOG (3 * STAGEB)       // 46080

__global__ __launch_bounds__(128, 4) void logits_mma_kernel(const float* __restrict__ bfc) {
    extern __shared__ char smem[];
    const uint32_t sb = smem_u32(smem);
    const int tid = threadIdx.x;
    const int wid = tid >> 5;
    const int lane = tid & 31;
    const int vb = blockIdx.x * VTILE;
    const int vrow0 = (wid & 1) * 32;
    const int brow0 = (wid >> 1) * 64;

    float d0[2][8][4] = {};

    // 768 granules/stage (W 256, h 512), 6 per thread
    auto load_stage = [&](int buf, int k0) {
        const uint32_t st = sb + buf * STAGEB;
#pragma unroll
        for (int i = 0; i < 6; ++i) {
            int lin = i * 128 + tid;
            if (lin < 256) {
                int row = lin >> 2, col = lin & 3;
                cp16(st + row * ROWB + col * 16,
                     g_W1 + (size_t)(vb + row) * 512 + k0 + col * 8);
            } else {
                int idx = lin - 256;
                int row = idx >> 2, col = idx & 3;
                cp16(st + WTILEB + row * ROWB + col * 16,
                     g_hn1 + (size_t)row * 512 + k0 + col * 8);
            }
        }
        CP_COMMIT();
    };

    load_stage(0, 0);
    load_stage(1, KC);

    for (int kc = 0; kc < 16; ++kc) {
        if (kc < 15) cp_wait<1>(); else cp_wait<0>();
        __syncthreads();
        if (kc + 2 < 16) load_stage((kc + 2) % 3, (kc + 2) * KC);
        const uint32_t st = sb + (kc % 3) * STAGEB;
#pragma unroll
        for (int ks = 0; ks < 2; ++ks) {
            const uint32_t kb = ks * 32;
            const int mat = lane >> 3;
            uint32_t a1[2][4];
#pragma unroll
            for (int mi = 0; mi < 2; ++mi) {
                const uint32_t row = vrow0 + mi * 16 + (mat & 1) * 8 + (lane & 7);
                ldsm4(a1[mi], st + row * ROWB + kb + (mat >> 1) * 16);
            }
            uint32_t b1[8][2];
#pragma unroll
            for (int j = 0; j < 4; ++j) {
                const uint32_t row = brow0 + j * 16 + (mat >> 1) * 8 + (lane & 7);
                uint32_t r[4];
                ldsm4(r, st + WTILEB + row * ROWB + kb + (mat & 1) * 16);
                b1[2 * j][0] = r[0]; b1[2 * j][1] = r[1];
                b1[2 * j + 1][0] = r[2]; b1[2 * j + 1][1] = r[3];
            }
#pragma unroll
            for (int mi = 0; mi < 2; ++mi)
#pragma unroll
                for (int nf = 0; nf < 8; ++nf)
                    mma16816(d0[mi][nf], a1[mi], b1[nf]);
        }
    }

    __syncthreads();
    float* slog = (float*)smem;            // [128][68] = 34816 <= 46080
#pragma unroll
    for (int mi = 0; mi < 2; ++mi) {
        const int vloc0 = vrow0 + mi * 16 + (lane >> 2);
        const float bias0 = bfc[vb + vloc0];
        const float bias1 = bfc[vb + vloc0 + 8];
#pragma unroll
        for (int nf = 0; nf < 8; ++nf) {
            const int b0 = brow0 + nf * 8 + 2 * (lane & 3);
            slog[(b0)     * 68 + vloc0]     = d0[mi][nf][0] + bias0;
            slog[(b0 + 1) * 68 + vloc0]     = d0[mi][nf][1] + bias0;
            slog[(b0)     * 68 + vloc0 + 8] = d0[mi][nf][2] + bias1;
            slog[(b0 + 1) * 68 + vloc0 + 8] = d0[mi][nf][3] + bias1;
        }
    }
    __syncthreads();
    {
        const float* col = slog + tid * 68;
        float v1 = col[0]; int i1 = 0;
        float v2 = -INFINITY;
#pragma unroll 8
        for (int v = 1; v < 64; ++v) {
            float x = col[v];
            if (x > v1) { v2 = v1; v1 = x; i1 = v; }
            else if (x > v2) v2 = x;
        }
        const size_t o = (size_t)blockIdx.x * 128 + tid;
        g_p1v[o] = v1;
        g_p1i[o] = vb + i1;
        g_p2v[o] = v2;
    }
}

// ---------------------------------------------------------------------------
__global__ __launch_bounds__(256) void fixup_kernel(
    const float* __restrict__ Wfc, const float* __restrict__ bfc,
    const float* __restrict__ emb, float* __restrict__ out, int step) {
    __shared__ float sh[512];
    __shared__ float sv[256];
    __shared__ int   si[256];
    __shared__ int   rows[128];
    __shared__ int   blks[16];
    __shared__ int   nrow, nblk;
    const int b = blockIdx.x, t = threadIdx.x;
    const int wid = t >> 5, lane = t & 31;

    for (int k = t; k < 512; k += 256) sh[k] = g_hnew[b * 512 + k];
    if (t == 0) { nrow = 0; nblk = 0; }

    float m = -INFINITY;
    for (int c = t; c < NVBLK2; c += 256) m = fmaxf(m, g_p1v[(size_t)c * 128 + b]);
    sv[t] = m;
    __syncthreads();
    for (int s = 128; s > 0; s >>= 1) {
        if (t < s) sv[t] = fmaxf(sv[t], sv[t + s]);
        __syncthreads();
    }
    const float gmax = sv[0];
    __syncthreads();
    const float thr = gmax - 0.01f * fmaxf(1.0f, fabsf(gmax));

    for (int c = t; c < NVBLK2; c += 256) {
        const size_t o = (size_t)c * 128 + b;
        if (g_p1v[o] >= thr) {
            int p = atomicAdd(&nrow, 1);
            if (p < 128) rows[p] = g_p1i[o];
        }
        if (g_p2v[o] >= thr) {
            int q = atomicAdd(&nblk, 1);
            if (q < 16) blks[q] = c;
        }
    }
    __syncthreads();
    const int nr = min(nrow, 128);
    const int nb = min(nblk, 16);

    float best = -INFINITY;
    int bi = 0x7fffffff;
    for (int ri = wid; ri < nr; ri += 8) {
        const int v = rows[ri];
        const float* w = Wfc + (size_t)v * 512;
        float acc = 0.0f;
#pragma unroll
        for (int j = 0; j < 4; ++j) {
            float4 wv = *(const float4*)(w + lane * 16 + j * 4);
            const float* hh = sh + lane * 16 + j * 4;
            acc += wv.x * hh[0] + wv.y * hh[1] + wv.z * hh[2] + wv.w * hh[3];
        }
#pragma unroll
        for (int o = 16; o; o >>= 1) acc += __shfl_xor_sync(0xffffffffu, acc, o);
        acc += bfc[v];
        if (lane == 0) {
            if (acc > best || (acc == best && v < bi)) { best = acc; bi = v; }
        }
    }
    for (int ci = 0; ci < nb; ++ci) {
        const int c = blks[ci];
        for (int r = wid; r < VTILE; r += 8) {
            const int v = c * VTILE + r;
            const float* w = Wfc + (size_t)v * 512;
            float acc = 0.0f;
#pragma unroll
            for (int j = 0; j < 4; ++j) {
                float4 wv = *(const float4*)(w + lane * 16 + j * 4);
                const float* hh = sh + lane * 16 + j * 4;
                acc += wv.x * hh[0] + wv.y * hh[1] + wv.z * hh[2] + wv.w * hh[3];
            }
#pragma unroll
            for (int o = 16; o; o >>= 1) acc += __shfl_xor_sync(0xffffffffu, acc, o);
            acc += bfc[v];
            if (lane == 0) {
                if (acc > best || (acc == best && v < bi)) { best = acc; bi = v; }
            }
        }
    }
    sv[t] = (lane == 0) ? best : -INFINITY;
    si[t] = (lane == 0) ? bi : 0x7fffffff;
    __syncthreads();
    for (int s = 128; s > 0; s >>= 1) {
        if (t < s) {
            float v = sv[t + s]; int ix = si[t + s];
            if (v > sv[t] || (v == sv[t] && ix < si[t])) { sv[t] = v; si[t] = ix; }
        }
        __syncthreads();
    }
    const int idx = si[0];
    if (t == 0) {
        out[b * TSTEPS + step] = (float)idx;
        out[BATCH * TSTEPS + b * TSTEPS + step] = sv[0];
    }
    for (int k = t; k < 512; k += 256) {
        float x = emb[(size_t)idx * 512 + k];
        __half x1 = __float2half_rn(x);
        __half x2 = __float2half_rn((x - __half2float(x1)) * 1024.0f);
        g_xh1[b * 1024 + k] = x1;
        g_xhs[b * 1024 + k] = __float2half_rn(__half2float(x1) + __half2float(x2));
        float h = sh[k];
        __half h1 = __float2half_rn(h);
        __half h2 = __float2half_rn((h - __half2float(h1)) * 1024.0f);
        g_xh1[b * 1024 + 512 + k] = h1;
        g_xhs[b * 1024 + 512 + k] = __float2half_rn(__half2float(h1) + __half2float(h2));
    }
}

// ---------------------------------------------------------------------------
extern "C" void kernel_launch(void* const* d_in, const int* in_sizes, int n_in,
                              void* d_out, int out_size) {
    const float* features = (const float*)d_in[0];
    const float* emb = (const float*)d_in[2];
    const float* Wih = (const float*)d_in[3];
    const float* Whh = (const float*)d_in[4];
    const float* bih = (const float*)d_in[5];
    const float* bhh = (const float*)d_in[6];
    const float* Wfc = (const float*)d_in[7];
    const float* bfc = (const float*)d_in[8];
    float* out = (float*)d_out;

    cudaFuncSetAttribute(logits_mma_kernel,
                         cudaFuncAttributeMaxDynamicSharedMemorySize, SMEM_LOG);
    cudaFuncSetAttribute(gates_mma_kernel,
                         cudaFuncAttributeMaxDynamicSharedMemorySize, SMEM_G);

    init_kernel<<<BATCH, 256>>>(features);
    wsplit_kernel<<<16000, 256>>>(Wfc);
    wsplit2_kernel<<<2048, 256>>>(Wih, Whh, bih, bhh);
    for (int t = 0; t < TSTEPS; ++t) {
        gates_mma_kernel<<<dim3(64, 4), 128, SMEM_G>>>();
        logits_mma_kernel<<<NVBLK2, 128, SMEM_LOG>>>(bfc);
        fixup_kernel<<<BATCH, 256>>>(Wfc, bfc, emb, out, t);
    }
}

// round 12
// speedup vs baseline: 1.2707x; 1.2707x over previous
#include <cuda_runtime.h>
#include <cuda_fp16.h>
#include <math.h>
#include <stdint.h>

#define BATCH   128
#define EMBED   512
#define HIDDEN  512
#define VOCAB   32000
#define TSTEPS  20
#define VTILE   128
#define NVBLK2  (VOCAB/VTILE)   // 250 logits blocks

// ---------------------------------------------------------------------------
// Persistent device scratch (re-written every launch -> deterministic)
__device__ float  g_hnew[BATCH * HIDDEN];
__device__ float  g_c[BATCH * HIDDEN];
__device__ float  g_p1v[NVBLK2 * BATCH];
__device__ int    g_p1i[NVBLK2 * BATCH];
__device__ float  g_p2v[NVBLK2 * BATCH];
// logits W, chunked: [vblk 250][kc 8][128 rows x 72 halves(144B)]
__device__ __half g_W1[250 * 8 * 9216];
// logits h, chunked: [kc 8][128 b x 72 halves]
__device__ __half g_hn1c[8 * 9216];
// gates W splits, chunked: [jb 64][kc 16][arr 2][32 rows x 72 halves]
__device__ __half g_Wg[64 * 16 * 2 * 2304];
// gates xh splits, chunked: [kc 16][arr 2][128 b x 72 halves]
__device__ __half g_Xg[16 * 2 * 9216];
__device__ float  g_bias[2048];

__device__ __forceinline__ float sigf(float x) { return 1.0f / (1.0f + expf(-x)); }
__device__ __forceinline__ int gxg_idx(int arr, int b, int kk) {
    return ((kk >> 6) * 2 + arr) * 9216 + b * 72 + (kk & 63);
}

// ---------------------------------------------------------------------------
__device__ __forceinline__ uint32_t smem_u32(const void* p) {
    uint32_t a;
    asm("{ .reg .u64 t; cvta.to.shared.u64 t, %1; cvt.u32.u64 %0, t; }" : "=r"(a) : "l"(p));
    return a;
}
__device__ __forceinline__ void bulkcp(uint32_t dst, const void* src,
                                       uint32_t bytes, uint32_t mbar) {
    asm volatile(
        "cp.async.bulk.shared::cluster.global.mbarrier::complete_tx::bytes "
        "[%0], [%1], %2, [%3];"
        :: "r"(dst), "l"(src), "r"(bytes), "r"(mbar) : "memory");
}
#define MBAR_INIT(a, n) \
    asm volatile("mbarrier.init.shared.b64 [%0], %1;" :: "r"(a), "r"(n) : "memory")
#define MBAR_EXPECT_TX(a, tx) \
    asm volatile("mbarrier.arrive.expect_tx.shared.b64 _, [%0], %1;" \
                 :: "r"(a), "r"(tx) : "memory")
__device__ __forceinline__ void mbar_wait(uint32_t addr, uint32_t parity) {
    asm volatile(
        "{\n\t.reg .pred P;\n\t"
        "W_%=:\n\t"
        "mbarrier.try_wait.parity.acquire.cta.shared::cta.b64 P, [%0], %1, 0x989680;\n\t"
        "@P bra.uni D_%=;\n\t"
        "bra.uni W_%=;\n\t"
        "D_%=:\n\t}"
        :: "r"(addr), "r"(parity) : "memory");
}
__device__ __forceinline__ void ldsm4(uint32_t* r, uint32_t a) {
    asm volatile("ldmatrix.sync.aligned.m8n8.x4.shared.b16 {%0,%1,%2,%3}, [%4];"
                 : "=r"(r[0]), "=r"(r[1]), "=r"(r[2]), "=r"(r[3]) : "r"(a));
}
__device__ __forceinline__ void mma16816(float* d, const uint32_t* a, const uint32_t* b) {
    asm volatile(
        "mma.sync.aligned.m16n8k16.row.col.f32.f16.f16.f32 "
        "{%0,%1,%2,%3}, {%4,%5,%6,%7}, {%8,%9}, {%0,%1,%2,%3};"
        : "+f"(d[0]), "+f"(d[1]), "+f"(d[2]), "+f"(d[3])
        : "r"(a[0]), "r"(a[1]), "r"(a[2]), "r"(a[3]), "r"(b[0]), "r"(b[1]));
}

// ---------------------------------------------------------------------------
__global__ void init_kernel(const float* __restrict__ features) {
    int b = blockIdx.x, t = threadIdx.x;
    for (int k = t; k < 512; k += 256) {
        float x = features[b * 512 + k];
        __half x1 = __float2half_rn(x);
        __half x2 = __float2half_rn((x - __half2float(x1)) * 1024.0f);
        g_Xg[gxg_idx(0, b, k)] = x1;
        g_Xg[gxg_idx(1, b, k)] = x2;
        g_Xg[gxg_idx(0, b, 512 + k)] = __float2half_rn(0.0f);
        g_Xg[gxg_idx(1, b, 512 + k)] = __float2half_rn(0.0f);
        g_hn1c[(k >> 6) * 9216 + b * 72 + (k & 63)] = __float2half_rn(0.0f);
        g_c[b * 512 + k]    = 0.0f;
        g_hnew[b * 512 + k] = 0.0f;
    }
}

// logits W -> fp16 chunked layout. 2,048,000 granules of 8 halves.
__global__ void wsplitL_kernel(const float* __restrict__ Wfc) {
    size_t i = (size_t)blockIdx.x * blockDim.x + threadIdx.x;
    int m  = (int)(i >> 6);
    int kg = ((int)i & 63) * 8;
    float4 a = *(const float4*)(Wfc + (size_t)m * 512 + kg);
    float4 c = *(const float4*)(Wfc + (size_t)m * 512 + kg + 4);
    __half2 h0 = __halves2half2(__float2half_rn(a.x), __float2half_rn(a.y));
    __half2 h1 = __halves2half2(__float2half_rn(a.z), __float2half_rn(a.w));
    __half2 h2 = __halves2half2(__float2half_rn(c.x), __float2half_rn(c.y));
    __half2 h3 = __halves2half2(__float2half_rn(c.z), __float2half_rn(c.w));
    int vblk = m >> 7, r = m & 127, kc = kg >> 6;
    __half2* dst = (__half2*)(g_W1 + (size_t)(vblk * 8 + kc) * 9216 + r * 72 + (kg & 63));
    dst[0] = h0; dst[1] = h1; dst[2] = h2; dst[3] = h3;
}

// gates Wcat -> 2-term split, chunked layout. 262,144 granules.
__global__ void wsplitG_kernel(const float* __restrict__ Wih,
                               const float* __restrict__ Whh,
                               const float* __restrict__ bih,
                               const float* __restrict__ bhh) {
    size_t i = (size_t)blockIdx.x * blockDim.x + threadIdx.x;
    int m  = (int)(i >> 7);
    int kg = ((int)i & 127) * 8;
    const float* src = (kg < 512) ? (Wih + (size_t)m * 512 + kg)
                                  : (Whh + (size_t)m * 512 + kg - 512);
    float v[8];
    *(float4*)(v)     = *(const float4*)(src);
    *(float4*)(v + 4) = *(const float4*)(src + 4);
    __half w1[8], w2[8];
#pragma unroll
    for (int q = 0; q < 8; ++q) {
        w1[q] = __float2half_rn(v[q]);
        w2[q] = __float2half_rn((v[q] - __half2float(w1[q])) * 1024.0f);
    }
    int g = m >> 9, j = m & 511;
    int jb = j >> 3, r = (g << 3) + (j & 7), kc = kg >> 6;
    size_t base0 = (size_t)((jb * 16 + kc) * 2 + 0) * 2304 + r * 72 + (kg & 63);
    size_t base1 = (size_t)((jb * 16 + kc) * 2 + 1) * 2304 + r * 72 + (kg & 63);
    *(uint4*)(g_Wg + base0) = *(uint4*)w1;
    *(uint4*)(g_Wg + base1) = *(uint4*)w2;
    if (kg == 0) g_bias[m] = bih[m] + bhh[m];
}

// ---------------------------------------------------------------------------
// HMMA gates (2-term split, 3 MMAs) + fused pointwise; bulk-copy loader.
// Tile 32 gate-rows x 32 batch, grid (64,4), 128 threads. 3-stage mbarrier ring.
#define GROWB   144
#define GW_T    4608
#define GB_T    4608
#define GSTAGE  18432
#define SMEM_G  (3 * GSTAGE)

__global__ __launch_bounds__(128, 2) void gates_mma_kernel() {
    extern __shared__ char smem[];
    __shared__ uint64_t mbf[3];
    const uint32_t sb = smem_u32(smem);
    const uint32_t mb0 = smem_u32(mbf);
    const int tid = threadIdx.x;
    const int wid = tid >> 5;
    const int lane = tid & 31;
    const int jb = blockIdx.x;
    const int j0 = jb * 8;
    const int n0 = blockIdx.y * 32;
    const int vrow0 = (wid & 1) * 16;
    const int bcol0 = (wid >> 1) * 16;

    if (tid == 0) {
        MBAR_INIT(mb0 + 0, 1); MBAR_INIT(mb0 + 8, 1); MBAR_INIT(mb0 + 16, 1);
    }
    __syncthreads();

    auto issue = [&](int buf, int kc) {
        const uint32_t st = sb + buf * GSTAGE;
        MBAR_EXPECT_TX(mb0 + buf * 8, GSTAGE);
        const __half* w0 = g_Wg + (size_t)((jb * 16 + kc) * 2 + 0) * 2304;
        const __half* w1 = g_Wg + (size_t)((jb * 16 + kc) * 2 + 1) * 2304;
        const __half* x0 = g_Xg + (size_t)(kc * 2 + 0) * 9216 + n0 * 72;
        const __half* x1 = g_Xg + (size_t)(kc * 2 + 1) * 9216 + n0 * 72;
        bulkcp(st,                   w0, 4608, mb0 + buf * 8);
        bulkcp(st + GW_T,            w1, 4608, mb0 + buf * 8);
        bulkcp(st + 2 * GW_T,        x0, 4608, mb0 + buf * 8);
        bulkcp(st + 2 * GW_T + GB_T, x1, 4608, mb0 + buf * 8);
    };

    if (tid == 0) { issue(0, 0); issue(1, 1); }

    float d0[2][4] = {};
    float d1[2][4] = {};
    int ph[3] = {0, 0, 0};

    for (int kc = 0; kc < 16; ++kc) {
        const int s = kc % 3;
        mbar_wait(mb0 + s * 8, ph[s]); ph[s] ^= 1;
        __syncthreads();
        if (tid == 0 && kc + 2 < 16) issue((kc + 2) % 3, kc + 2);
        const uint32_t st = sb + s * GSTAGE;
#pragma unroll
        for (int ks = 0; ks < 4; ++ks) {
            const uint32_t kb = ks * 32;
            const int mat = lane >> 3;
            uint32_t a1[4], a2[4];
            {
                const uint32_t row = vrow0 + (mat & 1) * 8 + (lane & 7);
                const uint32_t ao = row * GROWB + kb + (mat >> 1) * 16;
                ldsm4(a1, st + ao);
                ldsm4(a2, st + GW_T + ao);
            }
            uint32_t b1[2][2], b2[2][2];
            {
                const uint32_t row = bcol0 + (mat >> 1) * 8 + (lane & 7);
                const uint32_t bo = row * GROWB + kb + (mat & 1) * 16;
                uint32_t r[4];
                ldsm4(r, st + 2 * GW_T + bo);
                b1[0][0] = r[0]; b1[0][1] = r[1]; b1[1][0] = r[2]; b1[1][1] = r[3];
                ldsm4(r, st + 2 * GW_T + GB_T + bo);
                b2[0][0] = r[0]; b2[0][1] = r[1]; b2[1][0] = r[2]; b2[1][1] = r[3];
            }
#pragma unroll
            for (int nf = 0; nf < 2; ++nf) {
                mma16816(d0[nf], a1, b1[nf]);
                mma16816(d1[nf], a1, b2[nf]);
                mma16816(d1[nf], a2, b1[nf]);
            }
        }
    }

    __syncthreads();
    float* sg = (float*)smem;   // [32][33]
    const int r0 = vrow0 + (lane >> 2);
    const int r1 = r0 + 8;
#pragma unroll
    for (int nf = 0; nf < 2; ++nf) {
        const int c = bcol0 + nf * 8 + 2 * (lane & 3);
        sg[r0 * 33 + c]     = d0[nf][0] + d1[nf][0] * 0.0009765625f;
        sg[r0 * 33 + c + 1] = d0[nf][1] + d1[nf][1] * 0.0009765625f;
        sg[r1 * 33 + c]     = d0[nf][2] + d1[nf][2] * 0.0009765625f;
        sg[r1 * 33 + c + 1] = d0[nf][3] + d1[nf][3] * 0.0009765625f;
    }
    __syncthreads();
#pragma unroll
    for (int q = 0; q < 2; ++q) {
        const int idx = tid * 2 + q;
        const int jl = idx >> 5;
        const int bl = idx & 31;
        const int j = j0 + jl;
        const int b = n0 + bl;
        float ig = sigf(sg[(jl)      * 33 + bl] + g_bias[j]);
        float fg = sigf(sg[(8 + jl)  * 33 + bl] + g_bias[512 + j]);
        float gg = tanhf(sg[(16 + jl) * 33 + bl] + g_bias[1024 + j]);
        float og = sigf(sg[(24 + jl) * 33 + bl] + g_bias[1536 + j]);
        float c = fg * g_c[b * 512 + j] + ig * gg;
        g_c[b * 512 + j] = c;
        float h = og * tanhf(c);
        g_hnew[b * 512 + j] = h;
        g_hn1c[(j >> 6) * 9216 + b * 72 + (j & 63)] = __float2half_rn(h);
    }
}

// ---------------------------------------------------------------------------
// HMMA approx logits: per CTA 128 vocab x 128 batch, 256 threads (8 warps,
// warp tile 32v x 64b). Bulk-copy loader, 3-stage ring, per-column TOP-2.
#define LROWB   144
#define WTILEB  18432
#define HTILEB  18432
#define STAGEB  36864
#define SMEM_LOG (3 * STAGEB)

__global__ __launch_bounds__(256, 2) void logits_mma_kernel(const float* __restrict__ bfc) {
    extern __shared__ char smem[];
    __shared__ uint64_t mbf[3];
    __shared__ float pv1[256];
    __shared__ int   pi1[256];
    __shared__ float pv2[256];
    const uint32_t sb = smem_u32(smem);
    const uint32_t mb0 = smem_u32(mbf);
    const int tid = threadIdx.x;
    const int wid = tid >> 5;
    const int lane = tid & 31;
    const int vb = blockIdx.x * VTILE;
    const int vrow0 = (wid & 3) * 32;
    const int brow0 = (wid >> 2) * 64;

    if (tid == 0) {
        MBAR_INIT(mb0 + 0, 1); MBAR_INIT(mb0 + 8, 1); MBAR_INIT(mb0 + 16, 1);
    }
    __syncthreads();

    auto issue = [&](int buf, int kc) {
        const uint32_t st = sb + buf * STAGEB;
        MBAR_EXPECT_TX(mb0 + buf * 8, STAGEB);
        bulkcp(st,          g_W1 + (size_t)(blockIdx.x * 8 + kc) * 9216, WTILEB, mb0 + buf * 8);
        bulkcp(st + WTILEB, g_hn1c + (size_t)kc * 9216,                  HTILEB, mb0 + buf * 8);
    };

    if (tid == 0) { issue(0, 0); issue(1, 1); }

    float d0[2][8][4] = {};
    int ph[3] = {0, 0, 0};

    for (int kc = 0; kc < 8; ++kc) {
        const int s = kc % 3;
        mbar_wait(mb0 + s * 8, ph[s]); ph[s] ^= 1;
        __syncthreads();
        if (tid == 0 && kc + 2 < 8) issue((kc + 2) % 3, kc + 2);
        const uint32_t st = sb + s * STAGEB;
#pragma unroll
        for (int ks = 0; ks < 4; ++ks) {
            const uint32_t kb = ks * 32;
            const int mat = lane >> 3;
            uint32_t a1[2][4];
#pragma unroll
            for (int mi = 0; mi < 2; ++mi) {
                const uint32_t row = vrow0 + mi * 16 + (mat & 1) * 8 + (lane & 7);
                ldsm4(a1[mi], st + row * LROWB + kb + (mat >> 1) * 16);
            }
            uint32_t b1[8][2];
#pragma unroll
            for (int j = 0; j < 4; ++j) {
                const uint32_t row = brow0 + j * 16 + (mat >> 1) * 8 + (lane & 7);
                uint32_t r[4];
                ldsm4(r, st + WTILEB + row * LROWB + kb + (mat & 1) * 16);
                b1[2 * j][0] = r[0]; b1[2 * j][1] = r[1];
                b1[2 * j + 1][0] = r[2]; b1[2 * j + 1][1] = r[3];
            }
#pragma unroll
            for (int mi = 0; mi < 2; ++mi)
#pragma unroll
                for (int nf = 0; nf < 8; ++nf)
                    mma16816(d0[mi][nf], a1[mi], b1[nf]);
        }
    }

    // ---- epilogue: logits(+bias) into smem [b][128], per-column top-2 ----
    __syncthreads();
    float* slog = (float*)smem;            // [128][132] = 67584 <= SMEM_LOG
#pragma unroll
    for (int mi = 0; mi < 2; ++mi) {
        const int vloc0 = vrow0 + mi * 16 + (lane >> 2);
        const float bias0 = bfc[vb + vloc0];
        const float bias1 = bfc[vb + vloc0 + 8];
#pragma unroll
        for (int nf = 0; nf < 8; ++nf) {
            const int b0 = brow0 + nf * 8 + 2 * (lane & 3);
            slog[(b0)     * 132 + vloc0]     = d0[mi][nf][0] + bias0;
            slog[(b0 + 1) * 132 + vloc0]     = d0[mi][nf][1] + bias0;
            slog[(b0)     * 132 + vloc0 + 8] = d0[mi][nf][2] + bias1;
            slog[(b0 + 1) * 132 + vloc0 + 8] = d0[mi][nf][3] + bias1;
        }
    }
    __syncthreads();
    {
        const int c = tid & 127;
        const int half = tid >> 7;
        const float* col = slog + c * 132 + half * 64;
        float v1 = col[0]; int i1 = 0;
        float v2 = -INFINITY;
#pragma unroll 8
        for (int v = 1; v < 64; ++v) {
            float x = col[v];
            if (x > v1) { v2 = v1; v1 = x; i1 = v; }
            else if (x > v2) v2 = x;
        }
        pv1[tid] = v1; pi1[tid] = half * 64 + i1; pv2[tid] = v2;
    }
    __syncthreads();
    if (tid < 128) {
        const float v1a = pv1[tid],       v2a = pv2[tid];
        const int   i1a = pi1[tid];
        const float v1b = pv1[tid + 128], v2b = pv2[tid + 128];
        const int   i1b = pi1[tid + 128];
        float t1v, t2v; int t1i;
        if (v1b > v1a) { t1v = v1b; t1i = i1b; t2v = fmaxf(v1a, v2b); }
        else           { t1v = v1a; t1i = i1a; t2v = fmaxf(v1b, v2a); }
        const size_t o = (size_t)blockIdx.x * 128 + tid;
        g_p1v[o] = t1v;
        g_p1i[o] = vb + t1i;
        g_p2v[o] = t2v;
    }
}

// ---------------------------------------------------------------------------
// Fixup: gmax -> threshold -> exact fp32 dots for candidate rows; full-block
// rescan only if a block's top-2 clears thr. Output + gather + commit splits.
__global__ __launch_bounds__(256) void fixup_kernel(
    const float* __restrict__ Wfc, const float* __restrict__ bfc,
    const float* __restrict__ emb, float* __restrict__ out, int step) {
    __shared__ float sh[512];
    __shared__ float sv[256];
    __shared__ int   si[256];
    __shared__ int   rows[128];
    __shared__ int   blks[16];
    __shared__ int   nrow, nblk;
    const int b = blockIdx.x, t = threadIdx.x;
    const int wid = t >> 5, lane = t & 31;

    for (int k = t; k < 512; k += 256) sh[k] = g_hnew[b * 512 + k];
    if (t == 0) { nrow = 0; nblk = 0; }

    float m = -INFINITY;
    for (int c = t; c < NVBLK2; c += 256) m = fmaxf(m, g_p1v[(size_t)c * 128 + b]);
    sv[t] = m;
    __syncthreads();
    for (int s = 128; s > 0; s >>= 1) {
        if (t < s) sv[t] = fmaxf(sv[t], sv[t + s]);
        __syncthreads();
    }
    const float gmax = sv[0];
    __syncthreads();
    const float thr = gmax - 0.01f * fmaxf(1.0f, fabsf(gmax));

    for (int c = t; c < NVBLK2; c += 256) {
        const size_t o = (size_t)c * 128 + b;
        if (g_p1v[o] >= thr) {
            int p = atomicAdd(&nrow, 1);
            if (p < 128) rows[p] = g_p1i[o];
        }
        if (g_p2v[o] >= thr) {
            int q = atomicAdd(&nblk, 1);
            if (q < 16) blks[q] = c;
        }
    }
    __syncthreads();
    const int nr = min(nrow, 128);
    const int nb = min(nblk, 16);

    float best = -INFINITY;
    int bi = 0x7fffffff;
    for (int ri = wid; ri < nr; ri += 8) {
        const int v = rows[ri];
        const float* w = Wfc + (size_t)v * 512;
        float acc = 0.0f;
#pragma unroll
        for (int j = 0; j < 4; ++j) {
            float4 wv = *(const float4*)(w + lane * 16 + j * 4);
            const float* hh = sh + lane * 16 + j * 4;
            acc += wv.x * hh[0] + wv.y * hh[1] + wv.z * hh[2] + wv.w * hh[3];
        }
#pragma unroll
        for (int o = 16; o; o >>= 1) acc += __shfl_xor_sync(0xffffffffu, acc, o);
        acc += bfc[v];
        if (lane == 0) {
            if (acc > best || (acc == best && v < bi)) { best = acc; bi = v; }
        }
    }
    for (int ci = 0; ci < nb; ++ci) {
        const int c = blks[ci];
        for (int r = wid; r < VTILE; r += 8) {
            const int v = c * VTILE + r;
            const float* w = Wfc + (size_t)v * 512;
            float acc = 0.0f;
#pragma unroll
            for (int j = 0; j < 4; ++j) {
                float4 wv = *(const float4*)(w + lane * 16 + j * 4);
                const float* hh = sh + lane * 16 + j * 4;
                acc += wv.x * hh[0] + wv.y * hh[1] + wv.z * hh[2] + wv.w * hh[3];
            }
#pragma unroll
            for (int o = 16; o; o >>= 1) acc += __shfl_xor_sync(0xffffffffu, acc, o);
            acc += bfc[v];
            if (lane == 0) {
                if (acc > best || (acc == best && v < bi)) { best = acc; bi = v; }
            }
        }
    }
    sv[t] = (lane == 0) ? best : -INFINITY;
    si[t] = (lane == 0) ? bi : 0x7fffffff;
    __syncthreads();
    for (int s = 128; s > 0; s >>= 1) {
        if (t < s) {
            float v = sv[t + s]; int ix = si[t + s];
            if (v > sv[t] || (v == sv[t] && ix < si[t])) { sv[t] = v; si[t] = ix; }
        }
        __syncthreads();
    }
    const int idx = si[0];
    if (t == 0) {
        out[b * TSTEPS + step] = (float)idx;
        out[BATCH * TSTEPS + b * TSTEPS + step] = sv[0];
    }
    for (int k = t; k < 512; k += 256) {
        float x = emb[(size_t)idx * 512 + k];
        __half x1 = __float2half_rn(x);
        g_Xg[gxg_idx(0, b, k)] = x1;
        g_Xg[gxg_idx(1, b, k)] = __float2half_rn((x - __half2float(x1)) * 1024.0f);
        float h = sh[k];
        __half h1 = __float2half_rn(h);
        g_Xg[gxg_idx(0, b, 512 + k)] = h1;
        g_Xg[gxg_idx(1, b, 512 + k)] = __float2half_rn((h - __half2float(h1)) * 1024.0f);
    }
}

// ---------------------------------------------------------------------------
extern "C" void kernel_launch(void* const* d_in, const int* in_sizes, int n_in,
                              void* d_out, int out_size) {
    const float* features = (const float*)d_in[0];
    const float* emb = (const float*)d_in[2];
    const float* Wih = (const float*)d_in[3];
    const float* Whh = (const float*)d_in[4];
    const float* bih = (const float*)d_in[5];
    const float* bhh = (const float*)d_in[6];
    const float* Wfc = (const float*)d_in[7];
    const float* bfc = (const float*)d_in[8];
    float* out = (float*)d_out;

    cudaFuncSetAttribute(logits_mma_kernel,
                         cudaFuncAttributeMaxDynamicSharedMemorySize, SMEM_LOG);
    cudaFuncSetAttribute(gates_mma_kernel,
                         cudaFuncAttributeMaxDynamicSharedMemorySize, SMEM_G);

    init_kernel<<<BATCH, 256>>>(features);
    wsplitL_kernel<<<8000, 256>>>(Wfc);
    wsplitG_kernel<<<1024, 256>>>(Wih, Whh, bih, bhh);
    for (int t = 0; t < TSTEPS; ++t) {
        gates_mma_kernel<<<dim3(64, 4), 128, SMEM_G>>>();
        logits_mma_kernel<<<NVBLK2, 256, SMEM_LOG>>>(bfc);
        fixup_kernel<<<BATCH, 256>>>(Wfc, bfc, emb, out, t);
    }
}

// round 13
// speedup vs baseline: 1.3327x; 1.0488x over previous
#include <cuda_runtime.h>
#include <cuda_fp16.h>
#include <math.h>
#include <stdint.h>

#define BATCH   128
#define EMBED   512
#define HIDDEN  512
#define VOCAB   32000
#define TSTEPS  20
#define VTILE   128
#define NVBLK2  (VOCAB/VTILE)   // 250 logits blocks

// ---------------------------------------------------------------------------
// Persistent device scratch (re-written every launch -> deterministic)
__device__ float  g_hnew[BATCH * HIDDEN];
__device__ float  g_c[BATCH * HIDDEN];
__device__ float  g_p1v[NVBLK2 * BATCH];
__device__ int    g_p1i[NVBLK2 * BATCH];
__device__ float  g_p2v[NVBLK2 * BATCH];
// logits W, chunked: [vblk 250][kc 8][128 rows x 72 halves(144B)]
__device__ __half g_W1[250 * 8 * 9216];
// logits h, chunked: [kc 8][128 b x 72 halves]
__device__ __half g_hn1c[8 * 9216];
// gates W, chunked K=128: [jb 64][kc 8][arr 2][32 rows x 136 halves(272B)]
// arr0 = W1 (hi split), arr1 = Ws = fp16(W1 + W2)
__device__ __half g_Wg[64 * 8 * 2 * 32 * 136];
// gates x, chunked K=128: [kc 8][arr 2][128 b x 136 halves]; arr0=x1, arr1=xs
__device__ __half g_Xg[8 * 2 * 128 * 136];
__device__ float  g_bias[2048];

__device__ __forceinline__ float sigf(float x) { return 1.0f / (1.0f + expf(-x)); }
__device__ __forceinline__ int gxg_idx(int arr, int b, int k) {
    return (((k >> 7) * 2 + arr) * 128 + b) * 136 + (k & 127);
}

// ---------------------------------------------------------------------------
__device__ __forceinline__ uint32_t smem_u32(const void* p) {
    uint32_t a;
    asm("{ .reg .u64 t; cvta.to.shared.u64 t, %1; cvt.u32.u64 %0, t; }" : "=r"(a) : "l"(p));
    return a;
}
__device__ __forceinline__ void bulkcp(uint32_t dst, const void* src,
                                       uint32_t bytes, uint32_t mbar) {
    asm volatile(
        "cp.async.bulk.shared::cluster.global.mbarrier::complete_tx::bytes "
        "[%0], [%1], %2, [%3];"
        :: "r"(dst), "l"(src), "r"(bytes), "r"(mbar) : "memory");
}
#define MBAR_INIT(a, n) \
    asm volatile("mbarrier.init.shared.b64 [%0], %1;" :: "r"(a), "r"(n) : "memory")
#define MBAR_EXPECT_TX(a, tx) \
    asm volatile("mbarrier.arrive.expect_tx.shared.b64 _, [%0], %1;" \
                 :: "r"(a), "r"(tx) : "memory")
__device__ __forceinline__ void mbar_wait(uint32_t addr, uint32_t parity) {
    asm volatile(
        "{\n\t.reg .pred P;\n\t"
        "W_%=:\n\t"
        "mbarrier.try_wait.parity.acquire.cta.shared::cta.b64 P, [%0], %1, 0x989680;\n\t"
        "@P bra.uni D_%=;\n\t"
        "bra.uni W_%=;\n\t"
        "D_%=:\n\t}"
        :: "r"(addr), "r"(parity) : "memory");
}
__device__ __forceinline__ void ldsm4(uint32_t* r, uint32_t a) {
    asm volatile("ldmatrix.sync.aligned.m8n8.x4.shared.b16 {%0,%1,%2,%3}, [%4];"
                 : "=r"(r[0]), "=r"(r[1]), "=r"(r[2]), "=r"(r[3]) : "r"(a));
}
__device__ __forceinline__ void mma16816(float* d, const uint32_t* a, const uint32_t* b) {
    asm volatile(
        "mma.sync.aligned.m16n8k16.row.col.f32.f16.f16.f32 "
        "{%0,%1,%2,%3}, {%4,%5,%6,%7}, {%8,%9}, {%0,%1,%2,%3};"
        : "+f"(d[0]), "+f"(d[1]), "+f"(d[2]), "+f"(d[3])
        : "r"(a[0]), "r"(a[1]), "r"(a[2]), "r"(a[3]), "r"(b[0]), "r"(b[1]));
}

// ---------------------------------------------------------------------------
__global__ void init_kernel(const float* __restrict__ features) {
    int b = blockIdx.x, t = threadIdx.x;
    for (int k = t; k < 512; k += 256) {
        float x = features[b * 512 + k];
        __half x1 = __float2half_rn(x);
        __half x2 = __float2half_rn((x - __half2float(x1)) * 1024.0f);
        g_Xg[gxg_idx(0, b, k)] = x1;
        g_Xg[gxg_idx(1, b, k)] = __float2half_rn(__half2float(x1) + __half2float(x2));
        g_Xg[gxg_idx(0, b, 512 + k)] = __float2half_rn(0.0f);
        g_Xg[gxg_idx(1, b, 512 + k)] = __float2half_rn(0.0f);
        g_hn1c[(k >> 6) * 9216 + b * 72 + (k & 63)] = __float2half_rn(0.0f);
        g_c[b * 512 + k]    = 0.0f;
        g_hnew[b * 512 + k] = 0.0f;
    }
}

// logits W -> fp16 chunked layout. 2,048,000 granules of 8 halves.
__global__ void wsplitL_kernel(const float* __restrict__ Wfc) {
    size_t i = (size_t)blockIdx.x * blockDim.x + threadIdx.x;
    int m  = (int)(i >> 6);
    int kg = ((int)i & 63) * 8;
    float4 a = *(const float4*)(Wfc + (size_t)m * 512 + kg);
    float4 c = *(const float4*)(Wfc + (size_t)m * 512 + kg + 4);
    __half2 h0 = __halves2half2(__float2half_rn(a.x), __float2half_rn(a.y));
    __half2 h1 = __halves2half2(__float2half_rn(a.z), __float2half_rn(a.w));
    __half2 h2 = __halves2half2(__float2half_rn(c.x), __float2half_rn(c.y));
    __half2 h3 = __halves2half2(__float2half_rn(c.z), __float2half_rn(c.w));
    int vblk = m >> 7, r = m & 127, kc = kg >> 6;
    __half2* dst = (__half2*)(g_W1 + (size_t)(vblk * 8 + kc) * 9216 + r * 72 + (kg & 63));
    dst[0] = h0; dst[1] = h1; dst[2] = h2; dst[3] = h3;
}

// gates Wcat -> (W1, Ws) chunked K=128 layout. 262,144 granules of 8 halves.
__global__ void wsplitG_kernel(const float* __restrict__ Wih,
                               const float* __restrict__ Whh,
                               const float* __restrict__ bih,
                               const float* __restrict__ bhh) {
    size_t i = (size_t)blockIdx.x * blockDim.x + threadIdx.x;
    int m  = (int)(i >> 7);
    int kg = ((int)i & 127) * 8;
    const float* src = (kg < 512) ? (Wih + (size_t)m * 512 + kg)
                                  : (Whh + (size_t)m * 512 + kg - 512);
    float v[8];
    *(float4*)(v)     = *(const float4*)(src);
    *(float4*)(v + 4) = *(const float4*)(src + 4);
    __half w1[8], ws[8];
#pragma unroll
    for (int q = 0; q < 8; ++q) {
        w1[q] = __float2half_rn(v[q]);
        float r2 = (v[q] - __half2float(w1[q])) * 1024.0f;
        __half h2 = __float2half_rn(r2);
        ws[q] = __float2half_rn(__half2float(w1[q]) + __half2float(h2));
    }
    int g = m >> 9, j = m & 511;
    int jb = j >> 3, r = (g << 3) + (j & 7), kc = kg >> 7, kk = kg & 127;
    size_t base0 = ((size_t)((jb * 8 + kc) * 2 + 0) * 32 + r) * 136 + kk;
    size_t base1 = ((size_t)((jb * 8 + kc) * 2 + 1) * 32 + r) * 136 + kk;
    *(uint4*)(g_Wg + base0) = *(uint4*)w1;
    *(uint4*)(g_Wg + base1) = *(uint4*)ws;
    if (kg == 0) g_bias[m] = bih[m] + bhh[m];
}

// ---------------------------------------------------------------------------
// HMMA gates, 2-pass Ws trick: d0 = W1*x1, ds = Ws*xs;
// gate = d0*(1-2^-10) + ds*2^-10 + bias. Tile 32 gate-rows x 32 batch,
// grid (64,4), 128 threads. K-chunk 128, 8 chunks, 3-stage mbarrier ring.
#define GROWB   272
#define GW_T    8704                 // 32 rows x 272B
#define GB_T    8704
#define GSTAGE  (2 * GW_T + 2 * GB_T)  // 34816
#define SMEM_G  (3 * GSTAGE)           // 104448

__global__ __launch_bounds__(128, 2) void gates_mma_kernel() {
    extern __shared__ char smem[];
    __shared__ uint64_t mbf[3];
    const uint32_t sb = smem_u32(smem);
    const uint32_t mb0 = smem_u32(mbf);
    const int tid = threadIdx.x;
    const int wid = tid >> 5;
    const int lane = tid & 31;
    const int jb = blockIdx.x;
    const int j0 = jb * 8;
    const int n0 = blockIdx.y * 32;
    const int vrow0 = (wid & 1) * 16;
    const int bcol0 = (wid >> 1) * 16;

    if (tid == 0) {
        MBAR_INIT(mb0 + 0, 1); MBAR_INIT(mb0 + 8, 1); MBAR_INIT(mb0 + 16, 1);
    }
    __syncthreads();

    auto issue = [&](int buf, int kc) {
        const uint32_t st = sb + buf * GSTAGE;
        MBAR_EXPECT_TX(mb0 + buf * 8, GSTAGE);
        const __half* w0 = g_Wg + ((size_t)((jb * 8 + kc) * 2 + 0) * 32) * 136;
        const __half* w1 = g_Wg + ((size_t)((jb * 8 + kc) * 2 + 1) * 32) * 136;
        const __half* x0 = g_Xg + ((size_t)(kc * 2 + 0) * 128 + n0) * 136;
        const __half* x1 = g_Xg + ((size_t)(kc * 2 + 1) * 128 + n0) * 136;
        bulkcp(st,                   w0, GW_T, mb0 + buf * 8);
        bulkcp(st + GW_T,            w1, GW_T, mb0 + buf * 8);
        bulkcp(st + 2 * GW_T,        x0, GB_T, mb0 + buf * 8);
        bulkcp(st + 2 * GW_T + GB_T, x1, GB_T, mb0 + buf * 8);
    };

    if (tid == 0) { issue(0, 0); issue(1, 1); }

    float d0[2][4] = {};
    float ds[2][4] = {};
    int ph[3] = {0, 0, 0};

    for (int kc = 0; kc < 8; ++kc) {
        const int s = kc % 3;
        mbar_wait(mb0 + s * 8, ph[s]); ph[s] ^= 1;
        __syncthreads();
        if (tid == 0 && kc + 2 < 8) issue((kc + 2) % 3, kc + 2);
        const uint32_t st = sb + s * GSTAGE;
#pragma unroll
        for (int ks = 0; ks < 8; ++ks) {
            const uint32_t kb = ks * 32;
            const int mat = lane >> 3;
            uint32_t a1[4], as[4];
            {
                const uint32_t row = vrow0 + (mat & 1) * 8 + (lane & 7);
                const uint32_t ao = row * GROWB + kb + (mat >> 1) * 16;
                ldsm4(a1, st + ao);
                ldsm4(as, st + GW_T + ao);
            }
            uint32_t b1[2][2], bs[2][2];
            {
                const uint32_t row = bcol0 + (mat >> 1) * 8 + (lane & 7);
                const uint32_t bo = row * GROWB + kb + (mat & 1) * 16;
                uint32_t r[4];
                ldsm4(r, st + 2 * GW_T + bo);
                b1[0][0] = r[0]; b1[0][1] = r[1]; b1[1][0] = r[2]; b1[1][1] = r[3];
                ldsm4(r, st + 2 * GW_T + GB_T + bo);
                bs[0][0] = r[0]; bs[0][1] = r[1]; bs[1][0] = r[2]; bs[1][1] = r[3];
            }
#pragma unroll
            for (int nf = 0; nf < 2; ++nf) {
                mma16816(d0[nf], a1, b1[nf]);
                mma16816(ds[nf], as, bs[nf]);
            }
        }
    }

    __syncthreads();
    float* sg = (float*)smem;   // [32][33]
    const int r0 = vrow0 + (lane >> 2);
    const int r1 = r0 + 8;
    const float c0 = 0.9990234375f, c1 = 0.0009765625f;
#pragma unroll
    for (int nf = 0; nf < 2; ++nf) {
        const int c = bcol0 + nf * 8 + 2 * (lane & 3);
        sg[r0 * 33 + c]     = d0[nf][0] * c0 + ds[nf][0] * c1;
        sg[r0 * 33 + c + 1] = d0[nf][1] * c0 + ds[nf][1] * c1;
        sg[r1 * 33 + c]     = d0[nf][2] * c0 + ds[nf][2] * c1;
        sg[r1 * 33 + c + 1] = d0[nf][3] * c0 + ds[nf][3] * c1;
    }
    __syncthreads();
#pragma unroll
    for (int q = 0; q < 2; ++q) {
        const int idx = tid * 2 + q;
        const int jl = idx >> 5;
        const int bl = idx & 31;
        const int j = j0 + jl;
        const int b = n0 + bl;
        float ig = sigf(sg[(jl)      * 33 + bl] + g_bias[j]);
        float fg = sigf(sg[(8 + jl)  * 33 + bl] + g_bias[512 + j]);
        float gg = tanhf(sg[(16 + jl) * 33 + bl] + g_bias[1024 + j]);
        float og = sigf(sg[(24 + jl) * 33 + bl] + g_bias[1536 + j]);
        float c = fg * g_c[b * 512 + j] + ig * gg;
        g_c[b * 512 + j] = c;
        float h = og * tanhf(c);
        g_hnew[b * 512 + j] = h;
        g_hn1c[(j >> 6) * 9216 + b * 72 + (j & 63)] = __float2half_rn(h);
    }
}

// ---------------------------------------------------------------------------
// HMMA approx logits (unchanged from R12): per CTA 128v x 128b, 256 threads,
// warp tile 32v x 64b. Bulk-copy loader, 3-stage ring, per-column TOP-2.
#define LROWB   144
#define WTILEB  18432
#define HTILEB  18432
#define STAGEB  36864
#define SMEM_LOG (3 * STAGEB)

__global__ __launch_bounds__(256, 2) void logits_mma_kernel(const float* __restrict__ bfc) {
    extern __shared__ char smem[];
    __shared__ uint64_t mbf[3];
    __shared__ float pv1[256];
    __shared__ int   pi1[256];
    __shared__ float pv2[256];
    const uint32_t sb = smem_u32(smem);
    const uint32_t mb0 = smem_u32(mbf);
    const int tid = threadIdx.x;
    const int wid = tid >> 5;
    const int lane = tid & 31;
    const int vb = blockIdx.x * VTILE;
    const int vrow0 = (wid & 3) * 32;
    const int brow0 = (wid >> 2) * 64;

    if (tid == 0) {
        MBAR_INIT(mb0 + 0, 1); MBAR_INIT(mb0 + 8, 1); MBAR_INIT(mb0 + 16, 1);
    }
    __syncthreads();

    auto issue = [&](int buf, int kc) {
        const uint32_t st = sb + buf * STAGEB;
        MBAR_EXPECT_TX(mb0 + buf * 8, STAGEB);
        bulkcp(st,          g_W1 + (size_t)(blockIdx.x * 8 + kc) * 9216, WTILEB, mb0 + buf * 8);
        bulkcp(st + WTILEB, g_hn1c + (size_t)kc * 9216,                  HTILEB, mb0 + buf * 8);
    };

    if (tid == 0) { issue(0, 0); issue(1, 1); }

    float d0[2][8][4] = {};
    int ph[3] = {0, 0, 0};

    for (int kc = 0; kc < 8; ++kc) {
        const int s = kc % 3;
        mbar_wait(mb0 + s * 8, ph[s]); ph[s] ^= 1;
        __syncthreads();
        if (tid == 0 && kc + 2 < 8) issue((kc + 2) % 3, kc + 2);
        const uint32_t st = sb + s * STAGEB;
#pragma unroll
        for (int ks = 0; ks < 4; ++ks) {
            const uint32_t kb = ks * 32;
            const int mat = lane >> 3;
            uint32_t a1[2][4];
#pragma unroll
            for (int mi = 0; mi < 2; ++mi) {
                const uint32_t row = vrow0 + mi * 16 + (mat & 1) * 8 + (lane & 7);
                ldsm4(a1[mi], st + row * LROWB + kb + (mat >> 1) * 16);
            }
            uint32_t b1[8][2];
#pragma unroll
            for (int j = 0; j < 4; ++j) {
                const uint32_t row = brow0 + j * 16 + (mat >> 1) * 8 + (lane & 7);
                uint32_t r[4];
                ldsm4(r, st + WTILEB + row * LROWB + kb + (mat & 1) * 16);
                b1[2 * j][0] = r[0]; b1[2 * j][1] = r[1];
                b1[2 * j + 1][0] = r[2]; b1[2 * j + 1][1] = r[3];
            }
#pragma unroll
            for (int mi = 0; mi < 2; ++mi)
#pragma unroll
                for (int nf = 0; nf < 8; ++nf)
                    mma16816(d0[mi][nf], a1[mi], b1[nf]);
        }
    }

    __syncthreads();
    float* slog = (float*)smem;            // [128][132]
#pragma unroll
    for (int mi = 0; mi < 2; ++mi) {
        const int vloc0 = vrow0 + mi * 16 + (lane >> 2);
        const float bias0 = bfc[vb + vloc0];
        const float bias1 = bfc[vb + vloc0 + 8];
#pragma unroll
        for (int nf = 0; nf < 8; ++nf) {
            const int b0 = brow0 + nf * 8 + 2 * (lane & 3);
            slog[(b0)     * 132 + vloc0]     = d0[mi][nf][0] + bias0;
            slog[(b0 + 1) * 132 + vloc0]     = d0[mi][nf][1] + bias0;
            slog[(b0)     * 132 + vloc0 + 8] = d0[mi][nf][2] + bias1;
            slog[(b0 + 1) * 132 + vloc0 + 8] = d0[mi][nf][3] + bias1;
        }
    }
    __syncthreads();
    {
        const int c = tid & 127;
        const int half = tid >> 7;
        const float* col = slog + c * 132 + half * 64;
        float v1 = col[0]; int i1 = 0;
        float v2 = -INFINITY;
#pragma unroll 8
        for (int v = 1; v < 64; ++v) {
            float x = col[v];
            if (x > v1) { v2 = v1; v1 = x; i1 = v; }
            else if (x > v2) v2 = x;
        }
        pv1[tid] = v1; pi1[tid] = half * 64 + i1; pv2[tid] = v2;
    }
    __syncthreads();
    if (tid < 128) {
        const float v1a = pv1[tid],       v2a = pv2[tid];
        const int   i1a = pi1[tid];
        const float v1b = pv1[tid + 128], v2b = pv2[tid + 128];
        const int   i1b = pi1[tid + 128];
        float t1v, t2v; int t1i;
        if (v1b > v1a) { t1v = v1b; t1i = i1b; t2v = fmaxf(v1a, v2b); }
        else           { t1v = v1a; t1i = i1a; t2v = fmaxf(v1b, v2a); }
        const size_t o = (size_t)blockIdx.x * 128 + tid;
        g_p1v[o] = t1v;
        g_p1i[o] = vb + t1i;
        g_p2v[o] = t2v;
    }
}

// ---------------------------------------------------------------------------
// Fixup: gmax -> threshold -> exact fp32 dots for candidate rows; full-block
// rescan only if a block's top-2 clears thr. Output + gather + commit splits.
__global__ __launch_bounds__(256) void fixup_kernel(
    const float* __restrict__ Wfc, const float* __restrict__ bfc,
    const float* __restrict__ emb, float* __restrict__ out, int step) {
    __shared__ float sh[512];
    __shared__ float sv[256];
    __shared__ int   si[256];
    __shared__ int   rows[128];
    __shared__ int   blks[16];
    __shared__ int   nrow, nblk;
    const int b = blockIdx.x, t = threadIdx.x;
    const int wid = t >> 5, lane = t & 31;

    for (int k = t; k < 512; k += 256) sh[k] = g_hnew[b * 512 + k];
    if (t == 0) { nrow = 0; nblk = 0; }

    float m = -INFINITY;
    for (int c = t; c < NVBLK2; c += 256) m = fmaxf(m, g_p1v[(size_t)c * 128 + b]);
    sv[t] = m;
    __syncthreads();
    for (int s = 128; s > 0; s >>= 1) {
        if (t < s) sv[t] = fmaxf(sv[t], sv[t + s]);
        __syncthreads();
    }
    const float gmax = sv[0];
    __syncthreads();
    const float thr = gmax - 0.01f * fmaxf(1.0f, fabsf(gmax));

    for (int c = t; c < NVBLK2; c += 256) {
        const size_t o = (size_t)c * 128 + b;
        if (g_p1v[o] >= thr) {
            int p = atomicAdd(&nrow, 1);
            if (p < 128) rows[p] = g_p1i[o];
        }
        if (g_p2v[o] >= thr) {
            int q = atomicAdd(&nblk, 1);
            if (q < 16) blks[q] = c;
        }
    }
    __syncthreads();
    const int nr = min(nrow, 128);
    const int nb = min(nblk, 16);

    float best = -INFINITY;
    int bi = 0x7fffffff;
    for (int ri = wid; ri < nr; ri += 8) {
        const int v = rows[ri];
        const float* w = Wfc + (size_t)v * 512;
        float acc = 0.0f;
#pragma unroll
        for (int j = 0; j < 4; ++j) {
            float4 wv = *(const float4*)(w + lane * 16 + j * 4);
            const float* hh = sh + lane * 16 + j * 4;
            acc += wv.x * hh[0] + wv.y * hh[1] + wv.z * hh[2] + wv.w * hh[3];
        }
#pragma unroll
        for (int o = 16; o; o >>= 1) acc += __shfl_xor_sync(0xffffffffu, acc, o);
        acc += bfc[v];
        if (lane == 0) {
            if (acc > best || (acc == best && v < bi)) { best = acc; bi = v; }
        }
    }
    for (int ci = 0; ci < nb; ++ci) {
        const int c = blks[ci];
        for (int r = wid; r < VTILE; r += 8) {
            const int v = c * VTILE + r;
            const float* w = Wfc + (size_t)v * 512;
            float acc = 0.0f;
#pragma unroll
            for (int j = 0; j < 4; ++j) {
                float4 wv = *(const float4*)(w + lane * 16 + j * 4);
                const float* hh = sh + lane * 16 + j * 4;
                acc += wv.x * hh[0] + wv.y * hh[1] + wv.z * hh[2] + wv.w * hh[3];
            }
#pragma unroll
            for (int o = 16; o; o >>= 1) acc += __shfl_xor_sync(0xffffffffu, acc, o);
            acc += bfc[v];
            if (lane == 0) {
                if (acc > best || (acc == best && v < bi)) { best = acc; bi = v; }
            }
        }
    }
    sv[t] = (lane == 0) ? best : -INFINITY;
    si[t] = (lane == 0) ? bi : 0x7fffffff;
    __syncthreads();
    for (int s = 128; s > 0; s >>= 1) {
        if (t < s) {
            float v = sv[t + s]; int ix = si[t + s];
            if (v > sv[t] || (v == sv[t] && ix < si[t])) { sv[t] = v; si[t] = ix; }
        }
        __syncthreads();
    }
    const int idx = si[0];
    if (t == 0) {
        out[b * TSTEPS + step] = (float)idx;
        out[BATCH * TSTEPS + b * TSTEPS + step] = sv[0];
    }
    for (int k = t; k < 512; k += 256) {
        float x = emb[(size_t)idx * 512 + k];
        __half x1 = __float2half_rn(x);
        __half x2 = __float2half_rn((x - __half2float(x1)) * 1024.0f);
        g_Xg[gxg_idx(0, b, k)] = x1;
        g_Xg[gxg_idx(1, b, k)] = __float2half_rn(__half2float(x1) + __half2float(x2));
        float h = sh[k];
        __half h1 = __float2half_rn(h);
        __half h2 = __float2half_rn((h - __half2float(h1)) * 1024.0f);
        g_Xg[gxg_idx(0, b, 512 + k)] = h1;
        g_Xg[gxg_idx(1, b, 512 + k)] = __float2half_rn(__half2float(h1) + __half2float(h2));
    }
}

// ---------------------------------------------------------------------------
extern "C" void kernel_launch(void* const* d_in, const int* in_sizes, int n_in,
                              void* d_out, int out_size) {
    const float* features = (const float*)d_in[0];
    const float* emb = (const float*)d_in[2];
    const float* Wih = (const float*)d_in[3];
    const float* Whh = (const float*)d_in[4];
    const float* bih = (const float*)d_in[5];
    const float* bhh = (const float*)d_in[6];
    const float* Wfc = (const float*)d_in[7];
    const float* bfc = (const float*)d_in[8];
    float* out = (float*)d_out;

    cudaFuncSetAttribute(logits_mma_kernel,
                         cudaFuncAttributeMaxDynamicSharedMemorySize, SMEM_LOG);
    cudaFuncSetAttribute(gates_mma_kernel,
                         cudaFuncAttributeMaxDynamicSharedMemorySize, SMEM_G);

    init_kernel<<<BATCH, 256>>>(features);
    wsplitL_kernel<<<8000, 256>>>(Wfc);
    wsplitG_kernel<<<1024, 256>>>(Wih, Whh, bih, bhh);
    for (int t = 0; t < TSTEPS; ++t) {
        gates_mma_kernel<<<dim3(64, 4), 128, SMEM_G>>>();
        logits_mma_kernel<<<NVBLK2, 256, SMEM_LOG>>>(bfc);
        fixup_kernel<<<BATCH, 256>>>(Wfc, bfc, emb, out, t);
    }
}